// round 5
// baseline (speedup 1.0000x reference)
#include <cuda_runtime.h>
#include <math.h>

#define L    4096
#define DM   256
#define DI   512
#define DS   16
#define NB   2
#define CL   128
#define NCH  32

// ---------------- scratch (device globals) -----------------------------------
__device__ float g_A[DI*DS];
__device__ float g_upwT[512*256];
__device__ float g_xc[NB*DM*L];
__device__ float g_xi[NB*DI*L];
__device__ float g_z [NB*DI*L];
__device__ float g_u [NB*DI*L];
__device__ float g_dt[NB*DI*L];
__device__ float g_dbct[NB*48*L];
__device__ float g_S [NCH*NB*DI*DS];
__device__ float g_dts[NCH*NB*DI];
__device__ float g_H [NCH*NB*DI*DS];
__device__ float g_yout[NB*DI*L];
__device__ float g_xr[NB*DM*L];
__device__ float g_y2s[2][NB*128*L];
__device__ float g_mu[128];
__device__ float g_rstd[128];

// ---------------- prep -------------------------------------------------------
__global__ void prep_kernel(const float* __restrict__ Alog,
                            const float* __restrict__ upw) {
    int i = blockIdx.x * 256 + threadIdx.x;
    if (i < 512 * 256) {
        int j = i >> 8, c = i & 255;
        g_upwT[i] = upw[c * 512 + j];
    }
    if (i < DI * DS) g_A[i] = -expf(Alog[i]);
}

// ---------------- GEMM: C[m,n] = sum_k A[k*lda+m] * W[n*K+k] -----------------
// 128(m) x BN(n) tile, 256 threads, 8 x (BN/16) per thread, double-buffered.
// MODE 0: upsample | 1: in_proj | 2: x_proj | 3: dt_proj | 4: out_proj
template <int MODE, int BN>
__global__ void __launch_bounds__(256)
gemm_kernel(const float* __restrict__ Ain, const float* __restrict__ Bw,
            const float* __restrict__ bias, int N, int K, int lda, int aStride) {
    constexpr int TN = BN / 16;
    const int bz = blockIdx.z;
    const float* A;
    if (MODE == 0)      A = Ain    + (long)bz * aStride;
    else if (MODE == 1) A = g_xc   + (long)bz * aStride;
    else if (MODE == 2) A = g_u    + (long)bz * aStride;
    else if (MODE == 3) A = g_dbct + (long)bz * aStride;
    else                A = g_yout + (long)bz * aStride;
    const float* Bp = (MODE == 0) ? g_upwT : Bw;

    __shared__ float sm[4096 + 32 * BN];
    float* Asm = sm;                 // [2][16][128]
    float* Bsm = sm + 4096;          // [2][16][BN]
#define AS(buf,k,m) Asm[(buf)*2048 + (k)*128 + (m)]
#define BS(buf,k,n) Bsm[(buf)*(16*BN) + (k)*BN + (n)]
#define ES(n,m)     sm[(n)*132 + (m)]

    const int tid = threadIdx.x;
    const int m0 = blockIdx.y * 128;
    const int n0 = blockIdx.x * BN;
    const int tm = (tid >> 4) << 3;
    const int tn = (tid & 15) * TN;

    const int lak = tid >> 5;
    const int lam = (tid & 31) << 2;

    float acc[8][TN];
#pragma unroll
    for (int i = 0; i < 8; i++)
#pragma unroll
        for (int j = 0; j < TN; j++) acc[i][j] = 0.f;

    const int nk = K >> 4;

    if (BN == 128) {
        const int lbn = tid & 127;
        const int lbk = (tid >> 7) << 2;   // 0 or 4 (and +8)
        const int gbn = n0 + lbn;
        {
            float4 a0 = *(const float4*)(A + (long)lak * lda + m0 + lam);
            float4 a1 = *(const float4*)(A + (long)(lak + 8) * lda + m0 + lam);
            float4 b0 = make_float4(0.f,0.f,0.f,0.f), b1 = b0;
            if (gbn < N) {
                b0 = *(const float4*)(Bp + (long)gbn * K + lbk);
                b1 = *(const float4*)(Bp + (long)gbn * K + lbk + 8);
            }
            *(float4*)&AS(0, lak, lam) = a0;
            *(float4*)&AS(0, lak + 8, lam) = a1;
            BS(0, lbk + 0, lbn) = b0.x; BS(0, lbk + 1, lbn) = b0.y;
            BS(0, lbk + 2, lbn) = b0.z; BS(0, lbk + 3, lbn) = b0.w;
            BS(0, lbk + 8, lbn) = b1.x; BS(0, lbk + 9, lbn) = b1.y;
            BS(0, lbk +10, lbn) = b1.z; BS(0, lbk +11, lbn) = b1.w;
        }
        __syncthreads();
        for (int kt = 0; kt < nk; kt++) {
            const int cur = kt & 1;
            float4 na0, na1, nb0, nb1;
            if (kt + 1 < nk) {
                int k0 = (kt + 1) << 4;
                na0 = *(const float4*)(A + (long)(k0 + lak) * lda + m0 + lam);
                na1 = *(const float4*)(A + (long)(k0 + lak + 8) * lda + m0 + lam);
                nb0 = make_float4(0.f,0.f,0.f,0.f); nb1 = nb0;
                if (gbn < N) {
                    nb0 = *(const float4*)(Bp + (long)gbn * K + k0 + lbk);
                    nb1 = *(const float4*)(Bp + (long)gbn * K + k0 + lbk + 8);
                }
            }
#pragma unroll
            for (int kk = 0; kk < 16; kk++) {
                float4 av0 = *(float4*)&AS(cur, kk, tm);
                float4 av1 = *(float4*)&AS(cur, kk, tm + 4);
                float4 bv0 = *(float4*)&BS(cur, kk, tn);
                float4 bv1 = *(float4*)&BS(cur, kk, tn + 4);
                float a[8] = {av0.x,av0.y,av0.z,av0.w,av1.x,av1.y,av1.z,av1.w};
                float b[8] = {bv0.x,bv0.y,bv0.z,bv0.w,bv1.x,bv1.y,bv1.z,bv1.w};
#pragma unroll
                for (int i = 0; i < 8; i++)
#pragma unroll
                    for (int j = 0; j < 8; j++)
                        acc[i][j] = fmaf(a[i], b[j], acc[i][j]);
            }
            if (kt + 1 < nk) {
                int nxt = cur ^ 1;
                *(float4*)&AS(nxt, lak, lam) = na0;
                *(float4*)&AS(nxt, lak + 8, lam) = na1;
                BS(nxt, lbk + 0, lbn) = nb0.x; BS(nxt, lbk + 1, lbn) = nb0.y;
                BS(nxt, lbk + 2, lbn) = nb0.z; BS(nxt, lbk + 3, lbn) = nb0.w;
                BS(nxt, lbk + 8, lbn) = nb1.x; BS(nxt, lbk + 9, lbn) = nb1.y;
                BS(nxt, lbk +10, lbn) = nb1.z; BS(nxt, lbk +11, lbn) = nb1.w;
            }
            __syncthreads();
        }
    } else {  // BN == 64
        const int lbn = tid & 63;
        const int lbk = (tid >> 6) << 2;
        const int gbn = n0 + lbn;
        {
            float4 a0 = *(const float4*)(A + (long)lak * lda + m0 + lam);
            float4 a1 = *(const float4*)(A + (long)(lak + 8) * lda + m0 + lam);
            float4 b0 = make_float4(0.f,0.f,0.f,0.f);
            if (gbn < N) b0 = *(const float4*)(Bp + (long)gbn * K + lbk);
            *(float4*)&AS(0, lak, lam) = a0;
            *(float4*)&AS(0, lak + 8, lam) = a1;
            BS(0, lbk + 0, lbn) = b0.x; BS(0, lbk + 1, lbn) = b0.y;
            BS(0, lbk + 2, lbn) = b0.z; BS(0, lbk + 3, lbn) = b0.w;
        }
        __syncthreads();
        for (int kt = 0; kt < nk; kt++) {
            const int cur = kt & 1;
            float4 na0, na1, nb;
            if (kt + 1 < nk) {
                int k0 = (kt + 1) << 4;
                na0 = *(const float4*)(A + (long)(k0 + lak) * lda + m0 + lam);
                na1 = *(const float4*)(A + (long)(k0 + lak + 8) * lda + m0 + lam);
                nb = make_float4(0.f,0.f,0.f,0.f);
                if (gbn < N) nb = *(const float4*)(Bp + (long)gbn * K + k0 + lbk);
            }
#pragma unroll
            for (int kk = 0; kk < 16; kk++) {
                float4 av0 = *(float4*)&AS(cur, kk, tm);
                float4 av1 = *(float4*)&AS(cur, kk, tm + 4);
                float4 bv = *(float4*)&BS(cur, kk, tn);
                float a[8] = {av0.x,av0.y,av0.z,av0.w,av1.x,av1.y,av1.z,av1.w};
                float b[4] = {bv.x,bv.y,bv.z,bv.w};
#pragma unroll
                for (int i = 0; i < 8; i++)
#pragma unroll
                    for (int j = 0; j < 4; j++)
                        acc[i][j] = fmaf(a[i], b[j], acc[i][j]);
            }
            if (kt + 1 < nk) {
                int nxt = cur ^ 1;
                *(float4*)&AS(nxt, lak, lam) = na0;
                *(float4*)&AS(nxt, lak + 8, lam) = na1;
                BS(nxt, lbk + 0, lbn) = nb.x; BS(nxt, lbk + 1, lbn) = nb.y;
                BS(nxt, lbk + 2, lbn) = nb.z; BS(nxt, lbk + 3, lbn) = nb.w;
            }
            __syncthreads();
        }
    }

    if (MODE == 0) {
#pragma unroll
        for (int i = 0; i < 8; i++) {
#pragma unroll
            for (int j = 0; j < TN; j++) {
                int m = m0 + tm + i;
                int n = n0 + tn + j;
                int o = n >> 2, xx = (n >> 1) & 1, yy = n & 1;
                int h = m >> 5, w = m & 31;
                g_xc[((bz * DM + o) << 12) + (((h << 1) + xx) << 6) +
                     ((w << 1) + yy)] = acc[i][j] + bias[o];
            }
        }
        return;
    }

    // smem-staged transposed epilogue
    for (int part = 0; part < BN / 32; part++) {
        __syncthreads();
        if ((tn >> 5) == part) {
#pragma unroll
            for (int j = 0; j < TN; j++)
#pragma unroll
                for (int i = 0; i < 8; i++)
                    ES((tn & 31) + j, tm + i) = acc[i][j];
        }
        __syncthreads();
        int n = tid >> 3;
        int seg = (tid & 7) << 4;
        int gn = n0 + part * 32 + n;
        if (MODE == 2 && gn >= N) continue;
        int gm = m0 + seg;
        if (MODE == 1) {
            float* dst = (gn < DI) ? (g_xi + (((bz * DI + gn) << 12) + gm))
                                   : (g_z + (((bz * DI + (gn - DI)) << 12) + gm));
#pragma unroll
            for (int q = 0; q < 4; q++)
                ((float4*)dst)[q] = *(float4*)&ES(n, seg + (q << 2));
        } else if (MODE == 2) {
            float* dst = g_dbct + (bz * 48 + gn) * L + gm;
#pragma unroll
            for (int q = 0; q < 4; q++)
                ((float4*)dst)[q] = *(float4*)&ES(n, seg + (q << 2));
        } else if (MODE == 3) {
            float bn = bias[gn];
            float* dst = g_dt + ((bz * DI + gn) << 12) + gm;
#pragma unroll
            for (int q = 0; q < 4; q++) {
                float4 v = *(float4*)&ES(n, seg + (q << 2));
                float4 r; float t;
                t = v.x + bn; r.x = (t > 20.f) ? t : log1pf(__expf(t));
                t = v.y + bn; r.y = (t > 20.f) ? t : log1pf(__expf(t));
                t = v.z + bn; r.z = (t > 20.f) ? t : log1pf(__expf(t));
                t = v.w + bn; r.w = (t > 20.f) ? t : log1pf(__expf(t));
                ((float4*)dst)[q] = r;
            }
        } else {
            const float* src = g_xc + ((bz * DM + gn) << 12) + gm;
            float* dst = g_xr + ((bz * DM + gn) << 12) + gm;
#pragma unroll
            for (int q = 0; q < 4; q++) {
                float4 v = *(float4*)&ES(n, seg + (q << 2));
                float4 c = ((const float4*)src)[q];
                v.x += c.x; v.y += c.y; v.z += c.z; v.w += c.w;
                ((float4*)dst)[q] = v;
            }
        }
    }
#undef AS
#undef BS
#undef ES
}

// ---------------- skip -> xc channels 128..255 -------------------------------
__global__ void skipcopy_kernel(const float* __restrict__ skip) {
    int i = blockIdx.x * 256 + threadIdx.x;
    if (i >= NB * 128 * 1024) return;
    float4 v = reinterpret_cast<const float4*>(skip)[i];
    int b = i >> 17;
    int c = (i >> 10) & 127;
    int l4 = i & 1023;
    reinterpret_cast<float4*>(g_xc)[((b * 256 + 128 + c) << 10) + l4] = v;
}

// ---------------- depthwise causal conv1d (k=4) + SiLU -----------------------
__global__ void conv1d_kernel(const float* __restrict__ cw,
                              const float* __restrict__ cb) {
    int i4 = blockIdx.x * 256 + threadIdx.x;
    if (i4 >= NB * DI * (L / 4)) return;
    int l4 = i4 & 1023;
    int bd = i4 >> 10;
    int d = bd & (DI - 1);
    const float4* src = (const float4*)(g_xi + ((long)bd << 12));
    float4 c = src[l4];
    float4 p = (l4 > 0) ? src[l4 - 1] : make_float4(0.f, 0.f, 0.f, 0.f);
    float w0 = cw[d * 4], w1 = cw[d * 4 + 1], w2 = cw[d * 4 + 2], w3 = cw[d * 4 + 3];
    float bb = cb[d];
    float4 o;
    o.x = fmaf(p.y, w0, fmaf(p.z, w1, fmaf(p.w, w2, fmaf(c.x, w3, bb))));
    o.y = fmaf(p.z, w0, fmaf(p.w, w1, fmaf(c.x, w2, fmaf(c.y, w3, bb))));
    o.z = fmaf(p.w, w0, fmaf(c.x, w1, fmaf(c.y, w2, fmaf(c.z, w3, bb))));
    o.w = fmaf(c.x, w0, fmaf(c.y, w1, fmaf(c.z, w2, fmaf(c.w, w3, bb))));
    o.x = o.x / (1.f + __expf(-o.x));
    o.y = o.y / (1.f + __expf(-o.y));
    o.z = o.z / (1.f + __expf(-o.z));
    o.w = o.w / (1.f + __expf(-o.w));
    ((float4*)(g_u + ((long)bd << 12)))[l4] = o;
}

// ---------------- scan phase A ----------------------------------------------
__global__ void __launch_bounds__(128) scanA_kernel() {
    __shared__ float Bs[CL][17];
    const int b = blockIdx.z, c = blockIdx.y;
    const int d = blockIdx.x * 128 + threadIdx.x;
    const int t0 = c * CL;

    for (int i = threadIdx.x; i < DS * CL; i += 128) {
        int n = i >> 7, t = i & (CL - 1);
        Bs[t][n] = g_dbct[(b * 48 + 16 + n) * L + t0 + t];
    }
    __syncthreads();

    float Ar[DS];
#pragma unroll
    for (int n = 0; n < DS; n++) Ar[n] = g_A[d * DS + n];
    bool fast = true;
#pragma unroll
    for (int n = 1; n < DS; n++)
        fast = fast && (fabsf(Ar[n] - (n + 1) * Ar[0]) <=
                        4e-6f * fabsf(Ar[n]) + 1e-30f);

    float h[DS];
#pragma unroll
    for (int n = 0; n < DS; n++) h[n] = 0.f;
    float tsum = 0.f;
    const float* dtp = g_dt + ((b * DI + d) << 12) + t0;
    const float* up  = g_u  + ((b * DI + d) << 12) + t0;

    for (int t = 0; t < CL; t++) {
        float dtv = dtp[t], uv = up[t];
        tsum += dtv;
        float du = dtv * uv;
        if (fast) {
            float r = __expf(dtv * Ar[0]);
            float a = r;
#pragma unroll
            for (int n = 0; n < DS; n++) {
                h[n] = fmaf(a, h[n], du * Bs[t][n]);
                a *= r;
            }
        } else {
#pragma unroll
            for (int n = 0; n < DS; n++) {
                float a = __expf(dtv * Ar[n]);
                h[n] = fmaf(a, h[n], du * Bs[t][n]);
            }
        }
    }
    long so = (long)((c * NB + b) * DI + d) * DS;
#pragma unroll
    for (int n = 0; n < DS; n++) g_S[so + n] = h[n];
    g_dts[(c * NB + b) * DI + d] = tsum;
}

// ---------------- scan phase B ----------------------------------------------
__global__ void scanB_kernel() {
    int id = blockIdx.x * 256 + threadIdx.x;
    if (id >= NB * DI) return;
    int b = id / DI, d = id % DI;
    float Ar[DS];
#pragma unroll
    for (int n = 0; n < DS; n++) Ar[n] = g_A[d * DS + n];
    float h[DS];
#pragma unroll
    for (int n = 0; n < DS; n++) h[n] = 0.f;
    for (int c = 0; c < NCH; c++) {
        long o = (long)((c * NB + b) * DI + d) * DS;
#pragma unroll
        for (int n = 0; n < DS; n++) g_H[o + n] = h[n];
        float ts = g_dts[(c * NB + b) * DI + d];
#pragma unroll
        for (int n = 0; n < DS; n++)
            h[n] = fmaf(__expf(Ar[n] * ts), h[n], g_S[o + n]);
    }
}

// ---------------- scan phase C ----------------------------------------------
__global__ void __launch_bounds__(128) scanC_kernel(const float* __restrict__ Dp) {
    __shared__ float Bs[CL][17];
    __shared__ float Cs[CL][17];
    const int b = blockIdx.z, c = blockIdx.y;
    const int d = blockIdx.x * 128 + threadIdx.x;
    const int t0 = c * CL;

    for (int i = threadIdx.x; i < DS * CL; i += 128) {
        int n = i >> 7, t = i & (CL - 1);
        Bs[t][n] = g_dbct[(b * 48 + 16 + n) * L + t0 + t];
        Cs[t][n] = g_dbct[(b * 48 + 32 + n) * L + t0 + t];
    }
    __syncthreads();

    float Ar[DS];
#pragma unroll
    for (int n = 0; n < DS; n++) Ar[n] = g_A[d * DS + n];
    bool fast = true;
#pragma unroll
    for (int n = 1; n < DS; n++)
        fast = fast && (fabsf(Ar[n] - (n + 1) * Ar[0]) <=
                        4e-6f * fabsf(Ar[n]) + 1e-30f);

    float h[DS];
    long ho = (long)((c * NB + b) * DI + d) * DS;
#pragma unroll
    for (int n = 0; n < DS; n++) h[n] = g_H[ho + n];

    const float Dd = Dp[d];
    const int base = ((b * DI + d) << 12) + t0;
    const float* dtp = g_dt + base;
    const float* up  = g_u  + base;
    const float* zp  = g_z  + base;
    float* yo = g_yout + base;

    for (int t = 0; t < CL; t++) {
        float dtv = dtp[t], uv = up[t];
        float du = dtv * uv;
        float y = 0.f;
        if (fast) {
            float r = __expf(dtv * Ar[0]);
            float a = r;
#pragma unroll
            for (int n = 0; n < DS; n++) {
                h[n] = fmaf(a, h[n], du * Bs[t][n]);
                y = fmaf(h[n], Cs[t][n], y);
                a *= r;
            }
        } else {
#pragma unroll
            for (int n = 0; n < DS; n++) {
                float aa = __expf(dtv * Ar[n]);
                h[n] = fmaf(aa, h[n], du * Bs[t][n]);
                y = fmaf(h[n], Cs[t][n], y);
            }
        }
        float zv = zp[t];
        float sz = zv / (1.f + __expf(-zv));
        yo[t] = (y + uv * Dd) * sz;
    }
}

// ---------------- 3x3 conv: 128 thr, 2x4 px/thread, cin split in 2 -----------
__global__ void __launch_bounds__(128) conv3_kernel(const float* __restrict__ cw) {
    __shared__ float xs[4][34][36];
    __shared__ float ws[8][4][9];
    const int b = blockIdx.z;
    const int o0 = (blockIdx.y & 15) * 8;
    const int cs = blockIdx.y >> 4;
    const int cbase = cs * 128;
    const int ty0 = (blockIdx.x >> 1) * 32;
    const int tx0 = (blockIdx.x & 1) * 32;
    const int tid = threadIdx.x;
    const int py = (tid >> 3) << 1;   // 0..30
    const int px = (tid & 7) << 2;    // 0..28

    float acc[8][8];
#pragma unroll
    for (int o = 0; o < 8; o++)
#pragma unroll
        for (int p = 0; p < 8; p++) acc[o][p] = 0.f;

    for (int c0 = cbase; c0 < cbase + 128; c0 += 4) {
        for (int i = tid; i < 4 * 34 * 34; i += 128) {
            int cc = i / (34 * 34);
            int r = (i / 34) % 34;
            int col = i % 34;
            int gy = ty0 - 1 + r, gx = tx0 - 1 + col;
            float v = 0.f;
            if (gy >= 0 && gy < 64 && gx >= 0 && gx < 64)
                v = g_xr[((b * DM + c0 + cc) << 12) + (gy << 6) + gx];
            xs[cc][r][col] = v;
        }
        for (int i = tid; i < 288; i += 128) {
            int o = i / 36, rest = i % 36;
            int cc = rest / 9, k = rest % 9;
            ws[o][cc][k] = cw[((o0 + o) * 256 + c0 + cc) * 9 + k];
        }
        __syncthreads();
#pragma unroll
        for (int cc = 0; cc < 4; cc++) {
            float xv[4][6];
#pragma unroll
            for (int dy = 0; dy < 4; dy++)
#pragma unroll
                for (int dx = 0; dx < 6; dx++)
                    xv[dy][dx] = xs[cc][py + dy][px + dx];
#pragma unroll
            for (int o = 0; o < 8; o++) {
                float w[9];
#pragma unroll
                for (int k = 0; k < 9; k++) w[k] = ws[o][cc][k];
#pragma unroll
                for (int sy = 0; sy < 2; sy++)
#pragma unroll
                    for (int sx = 0; sx < 4; sx++) {
                        float s = acc[o][sy * 4 + sx];
#pragma unroll
                        for (int kh = 0; kh < 3; kh++)
#pragma unroll
                            for (int kw = 0; kw < 3; kw++)
                                s = fmaf(xv[sy + kh][sx + kw], w[kh * 3 + kw], s);
                        acc[o][sy * 4 + sx] = s;
                    }
            }
        }
        __syncthreads();
    }
#pragma unroll
    for (int o = 0; o < 8; o++) {
#pragma unroll
        for (int sy = 0; sy < 2; sy++) {
            float4 v = make_float4(acc[o][sy * 4], acc[o][sy * 4 + 1],
                                   acc[o][sy * 4 + 2], acc[o][sy * 4 + 3]);
            *(float4*)&g_y2s[cs][((b * 128 + o0 + o) << 12) +
                                 ((ty0 + py + sy) << 6) + tx0 + px] = v;
        }
    }
}

// ---------------- BN statistics per channel ----------------------------------
__global__ void bnstat_kernel() {
    __shared__ float ss[256], ss2[256];
    int ch = blockIdx.x;
    float s = 0.f, s2 = 0.f;
    for (int i = threadIdx.x; i < NB * (L / 4); i += 256) {
        int b = i >> 10, p4 = i & 1023;
        int off4 = ((b * 128 + ch) << 10) + p4;
        float4 a = ((const float4*)g_y2s[0])[off4];
        float4 c = ((const float4*)g_y2s[1])[off4];
        float v;
        v = a.x + c.x; s += v; s2 += v * v;
        v = a.y + c.y; s += v; s2 += v * v;
        v = a.z + c.z; s += v; s2 += v * v;
        v = a.w + c.w; s += v; s2 += v * v;
    }
    ss[threadIdx.x] = s;
    ss2[threadIdx.x] = s2;
    __syncthreads();
    for (int st = 128; st > 0; st >>= 1) {
        if (threadIdx.x < st) {
            ss[threadIdx.x] += ss[threadIdx.x + st];
            ss2[threadIdx.x] += ss2[threadIdx.x + st];
        }
        __syncthreads();
    }
    if (threadIdx.x == 0) {
        float inv = 1.f / (NB * L);
        float mean = ss[0] * inv;
        float var = ss2[0] * inv - mean * mean;
        g_mu[ch] = mean;
        g_rstd[ch] = rsqrtf(var + 1e-5f);
    }
}

// ---------------- BN apply + exact GELU --------------------------------------
__global__ void bngelu_kernel(const float* __restrict__ gamma,
                              const float* __restrict__ beta,
                              float* __restrict__ out) {
    int i4 = blockIdx.x * 256 + threadIdx.x;
    if (i4 >= NB * 128 * (L / 4)) return;
    int ch = (i4 >> 10) & 127;
    float sc = g_rstd[ch] * gamma[ch];
    float sh = beta[ch] - g_mu[ch] * sc;
    float4 a = ((const float4*)g_y2s[0])[i4];
    float4 b = ((const float4*)g_y2s[1])[i4];
    float4 r;
    float v;
    v = fmaf(a.x + b.x, sc, sh); r.x = 0.5f * v * (1.f + erff(v * 0.70710678f));
    v = fmaf(a.y + b.y, sc, sh); r.y = 0.5f * v * (1.f + erff(v * 0.70710678f));
    v = fmaf(a.z + b.z, sc, sh); r.z = 0.5f * v * (1.f + erff(v * 0.70710678f));
    v = fmaf(a.w + b.w, sc, sh); r.w = 0.5f * v * (1.f + erff(v * 0.70710678f));
    ((float4*)out)[i4] = r;
}

// ---------------- launch ------------------------------------------------------
extern "C" void kernel_launch(void* const* d_in, const int* in_sizes, int n_in,
                              void* d_out, int out_size) {
    const float* x        = (const float*)d_in[0];
    const float* skip     = (const float*)d_in[1];
    const float* up_w     = (const float*)d_in[2];
    const float* up_b     = (const float*)d_in[3];
    const float* in_proj  = (const float*)d_in[4];
    const float* conv1d_w = (const float*)d_in[5];
    const float* conv1d_b = (const float*)d_in[6];
    const float* x_proj   = (const float*)d_in[7];
    const float* dt_proj  = (const float*)d_in[8];
    const float* dt_b     = (const float*)d_in[9];
    const float* A_log    = (const float*)d_in[10];
    const float* Dp       = (const float*)d_in[11];
    const float* out_proj = (const float*)d_in[12];
    const float* conv_w   = (const float*)d_in[13];
    const float* bn_g     = (const float*)d_in[15];
    const float* bn_b     = (const float*)d_in[16];
    float* out = (float*)d_out;

    prep_kernel<<<512, 256>>>(A_log, up_w);

    // upsample: M=1024, N=512, K=256
    gemm_kernel<0, 128><<<dim3(4, 8, NB), 256>>>(x, nullptr, up_b, 512, 256,
                                                 1024, 256 * 1024);
    skipcopy_kernel<<<1024, 256>>>(skip);

    // in_proj: M=4096, N=1024, K=256
    gemm_kernel<1, 128><<<dim3(8, 32, NB), 256>>>(nullptr, in_proj, nullptr,
                                                  1024, 256, L, DM * L);
    conv1d_kernel<<<(NB * DI * L / 4) / 256, 256>>>(conv1d_w, conv1d_b);

    // x_proj: M=4096, N=48, K=512
    gemm_kernel<2, 64><<<dim3(1, 32, NB), 256>>>(nullptr, x_proj, nullptr, 48,
                                                 DI, L, DI * L);
    // dt_proj: M=4096, N=512, K=16
    gemm_kernel<3, 128><<<dim3(4, 32, NB), 256>>>(nullptr, dt_proj, dt_b, DI,
                                                  16, L, 48 * L);

    scanA_kernel<<<dim3(4, NCH, NB), 128>>>();
    scanB_kernel<<<4, 256>>>();
    scanC_kernel<<<dim3(4, NCH, NB), 128>>>(Dp);

    // out_proj (+residual): M=4096, N=256, K=512
    gemm_kernel<4, 128><<<dim3(2, 32, NB), 256>>>(nullptr, out_proj, nullptr,
                                                  DM, DI, L, DI * L);

    conv3_kernel<<<dim3(4, 32, NB), 128>>>(conv_w);
    bnstat_kernel<<<128, 256>>>();
    bngelu_kernel<<<(NB * 128 * L / 4) / 256, 256>>>(bn_g, bn_b, out);
}

// round 7
// speedup vs baseline: 1.2373x; 1.2373x over previous
#include <cuda_runtime.h>
#include <math.h>

#define L    4096
#define DM   256
#define DI   512
#define DS   16
#define NB   2
#define CL   128
#define NCH  32

// ---------------- scratch (device globals) -----------------------------------
__device__ float g_A[DI*DS];
__device__ float g_upwT[512*256];
__device__ float g_xc[NB*DM*L];        // (b, c, l)  l-contig (for conv3/residual)
__device__ float g_xi[NB*L*DI];        // (b, l, d)  d-contig
__device__ float g_z [NB*L*DI];        // (b, l, d)
__device__ float g_u [NB*L*DI];        // (b, l, d)
__device__ float g_dt[NB*L*DI];        // (b, l, d)
__device__ float g_dbc[NB*L*48];       // (b, l, 48)
__device__ float g_S [NCH*NB*DI*DS];
__device__ float g_dts[NCH*NB*DI];
__device__ float g_H [NCH*NB*DI*DS];
__device__ float g_yout[NB*L*DI];      // (b, l, d)
__device__ float g_xr[NB*DM*L];        // (b, c, l)
__device__ float g_y2s[2][NB*128*L];
__device__ float g_mu[128];
__device__ float g_rstd[128];

// ---------------- prep: A, up_w transpose, skip copy -------------------------
__global__ void prep_kernel(const float* __restrict__ Alog,
                            const float* __restrict__ upw,
                            const float* __restrict__ skip) {
    int i = blockIdx.x * 256 + threadIdx.x;
    if (i < 512 * 256) {
        int j = i >> 8, c = i & 255;
        g_upwT[i] = upw[c * 512 + j];
    }
    if (i < DI * DS) g_A[i] = -expf(Alog[i]);
    if (i < NB * 128 * 1024) {
        float4 v = reinterpret_cast<const float4*>(skip)[i];
        int b = i >> 17;
        int c = (i >> 10) & 127;
        int l4 = i & 1023;
        reinterpret_cast<float4*>(g_xc)[((b * 256 + 128 + c) << 10) + l4] = v;
    }
}

// ---------------- GEMM: C[m,n] = sum_k A(k,m) * W[n*K+k] ---------------------
// 128(m) x 64(n) tile, 256 threads, 8x4 microtile, double-buffered smem.
// ALAYOUT 0: A[k*lda + m] (m contig).  ALAYOUT 1: A[m*lda + k] (k contig).
// MODE 0: upsample scatter | 1: in_proj split (l,d) | 2: x_proj (l,48)
// MODE 3: dt_proj softplus (l,d)      | 4: out_proj residual -> (c,l)
template <int MODE, int ALAYOUT>
__global__ void __launch_bounds__(256)
gemm_kernel(const float* __restrict__ Ain, const float* __restrict__ Bw,
            const float* __restrict__ bias, int N, int K, int lda, int aStride) {
    const int bz = blockIdx.z;
    const float* A;
    if (MODE == 0)      A = Ain    + (long)bz * aStride;
    else if (MODE == 1) A = g_xc   + (long)bz * aStride;
    else if (MODE == 2) A = g_u    + (long)bz * aStride;
    else if (MODE == 3) A = g_dbc  + (long)bz * aStride;
    else                A = g_yout + (long)bz * aStride;
    const float* Bp = (MODE == 0) ? g_upwT : Bw;

    __shared__ float sm[6144];   // As[2][16][128] | Bs[2][16][64]; ES overlay
#define AS(buf,k,m) sm[(buf)*2048 + (k)*128 + (m)]
#define BS(buf,k,n) sm[4096 + (buf)*1024 + (k)*64 + (n)]
#define ES(n,m)     sm[(n)*132 + (m)]

    const int tid = threadIdx.x;
    const int m0 = blockIdx.y * 128;
    const int n0 = blockIdx.x * 64;
    const int tm = (tid >> 4) << 3;
    const int tn = (tid & 15) << 2;

    // loader indices
    const int lak = tid >> 5;            // ALAYOUT0: k row 0..7 (+8)
    const int lam = (tid & 31) << 2;     // ALAYOUT0: m col
    const int lrow = tid >> 2;           // ALAYOUT1: m row 0..63 (+64)
    const int lcol = (tid & 3) << 2;     // ALAYOUT1: k col 0,4,8,12
    const int lbn = tid & 63;
    const int lbk = (tid >> 6) << 2;
    const int gbn = n0 + lbn;

    float acc[8][4];
#pragma unroll
    for (int i = 0; i < 8; i++)
#pragma unroll
        for (int j = 0; j < 4; j++) acc[i][j] = 0.f;

    const int nk = K >> 4;

    // preload tile 0
    {
        float4 a0, a1;
        if (ALAYOUT == 0) {
            a0 = *(const float4*)(A + (long)lak * lda + m0 + lam);
            a1 = *(const float4*)(A + (long)(lak + 8) * lda + m0 + lam);
        } else {
            a0 = *(const float4*)(A + (long)(m0 + lrow) * lda + lcol);
            a1 = *(const float4*)(A + (long)(m0 + lrow + 64) * lda + lcol);
        }
        float4 b0 = make_float4(0.f, 0.f, 0.f, 0.f);
        if (gbn < N) b0 = *(const float4*)(Bp + (long)gbn * K + lbk);
        if (ALAYOUT == 0) {
            *(float4*)&AS(0, lak, lam) = a0;
            *(float4*)&AS(0, lak + 8, lam) = a1;
        } else {
            AS(0, lcol + 0, lrow) = a0.x; AS(0, lcol + 1, lrow) = a0.y;
            AS(0, lcol + 2, lrow) = a0.z; AS(0, lcol + 3, lrow) = a0.w;
            AS(0, lcol + 0, lrow + 64) = a1.x; AS(0, lcol + 1, lrow + 64) = a1.y;
            AS(0, lcol + 2, lrow + 64) = a1.z; AS(0, lcol + 3, lrow + 64) = a1.w;
        }
        BS(0, lbk + 0, lbn) = b0.x; BS(0, lbk + 1, lbn) = b0.y;
        BS(0, lbk + 2, lbn) = b0.z; BS(0, lbk + 3, lbn) = b0.w;
    }
    __syncthreads();

    for (int kt = 0; kt < nk; kt++) {
        const int cur = kt & 1;
        float4 na0, na1, nb;
        if (kt + 1 < nk) {
            int k0 = (kt + 1) << 4;
            if (ALAYOUT == 0) {
                na0 = *(const float4*)(A + (long)(k0 + lak) * lda + m0 + lam);
                na1 = *(const float4*)(A + (long)(k0 + lak + 8) * lda + m0 + lam);
            } else {
                na0 = *(const float4*)(A + (long)(m0 + lrow) * lda + k0 + lcol);
                na1 = *(const float4*)(A + (long)(m0 + lrow + 64) * lda + k0 + lcol);
            }
            nb = make_float4(0.f, 0.f, 0.f, 0.f);
            if (gbn < N) nb = *(const float4*)(Bp + (long)gbn * K + k0 + lbk);
        }
#pragma unroll
        for (int kk = 0; kk < 16; kk++) {
            float4 av0 = *(float4*)&AS(cur, kk, tm);
            float4 av1 = *(float4*)&AS(cur, kk, tm + 4);
            float4 bv = *(float4*)&BS(cur, kk, tn);
            float a[8] = {av0.x, av0.y, av0.z, av0.w, av1.x, av1.y, av1.z, av1.w};
            float b[4] = {bv.x, bv.y, bv.z, bv.w};
#pragma unroll
            for (int i = 0; i < 8; i++)
#pragma unroll
                for (int j = 0; j < 4; j++)
                    acc[i][j] = fmaf(a[i], b[j], acc[i][j]);
        }
        if (kt + 1 < nk) {
            int nxt = cur ^ 1;
            if (ALAYOUT == 0) {
                *(float4*)&AS(nxt, lak, lam) = na0;
                *(float4*)&AS(nxt, lak + 8, lam) = na1;
            } else {
                AS(nxt, lcol + 0, lrow) = na0.x; AS(nxt, lcol + 1, lrow) = na0.y;
                AS(nxt, lcol + 2, lrow) = na0.z; AS(nxt, lcol + 3, lrow) = na0.w;
                AS(nxt, lcol + 0, lrow + 64) = na1.x;
                AS(nxt, lcol + 1, lrow + 64) = na1.y;
                AS(nxt, lcol + 2, lrow + 64) = na1.z;
                AS(nxt, lcol + 3, lrow + 64) = na1.w;
            }
            BS(nxt, lbk + 0, lbn) = nb.x; BS(nxt, lbk + 1, lbn) = nb.y;
            BS(nxt, lbk + 2, lbn) = nb.z; BS(nxt, lbk + 3, lbn) = nb.w;
        }
        __syncthreads();
    }

    if (MODE == 0) {
        // scatter: n -> (o,x,y), m -> (h,w); write up + bias into g_xc (c,l)
#pragma unroll
        for (int i = 0; i < 8; i++) {
#pragma unroll
            for (int j = 0; j < 4; j++) {
                int m = m0 + tm + i;
                int n = n0 + tn + j;
                int o = n >> 2, xx = (n >> 1) & 1, yy = n & 1;
                int h = m >> 5, w = m & 31;
                g_xc[((bz * DM + o) << 12) + (((h << 1) + xx) << 6) +
                     ((w << 1) + yy)] = acc[i][j] + bias[o];
            }
        }
        return;
    }

    if (MODE == 1) {
        int gn = n0 + tn;
#pragma unroll
        for (int i = 0; i < 8; i++) {
            int m = m0 + tm + i;
            float4 v = make_float4(acc[i][0], acc[i][1], acc[i][2], acc[i][3]);
            if (gn < DI)
                *(float4*)(g_xi + ((long)bz * L + m) * DI + gn) = v;
            else
                *(float4*)(g_z + ((long)bz * L + m) * DI + gn - DI) = v;
        }
        return;
    }
    if (MODE == 2) {
        int gn = n0 + tn;
        if (gn < 48) {
#pragma unroll
            for (int i = 0; i < 8; i++) {
                int m = m0 + tm + i;
                float4 v = make_float4(acc[i][0], acc[i][1], acc[i][2], acc[i][3]);
                *(float4*)(g_dbc + ((long)bz * L + m) * 48 + gn) = v;
            }
        }
        return;
    }
    if (MODE == 3) {
        int gn = n0 + tn;
        float4 bn = *(const float4*)(bias + gn);
#pragma unroll
        for (int i = 0; i < 8; i++) {
            int m = m0 + tm + i;
            float4 r; float t;
            t = acc[i][0] + bn.x; r.x = (t > 20.f) ? t : log1pf(__expf(t));
            t = acc[i][1] + bn.y; r.y = (t > 20.f) ? t : log1pf(__expf(t));
            t = acc[i][2] + bn.z; r.z = (t > 20.f) ? t : log1pf(__expf(t));
            t = acc[i][3] + bn.w; r.w = (t > 20.f) ? t : log1pf(__expf(t));
            *(float4*)(g_dt + ((long)bz * L + m) * DI + gn) = r;
        }
        return;
    }

    // MODE 4: smem-staged transposed epilogue -> xr (c, l) with residual
    for (int part = 0; part < 2; part++) {
        __syncthreads();
        if ((tn >> 5) == part) {
#pragma unroll
            for (int j = 0; j < 4; j++)
#pragma unroll
                for (int i = 0; i < 8; i++)
                    ES((tn & 31) + j, tm + i) = acc[i][j];
        }
        __syncthreads();
        int n = tid >> 3;
        int seg = (tid & 7) << 4;
        int gn = n0 + part * 32 + n;
        int gm = m0 + seg;
        const float* src = g_xc + ((bz * DM + gn) << 12) + gm;
        float* dst = g_xr + ((bz * DM + gn) << 12) + gm;
#pragma unroll
        for (int q = 0; q < 4; q++) {
            float4 v = *(float4*)&ES(n, seg + (q << 2));
            float4 c = ((const float4*)src)[q];
            v.x += c.x; v.y += c.y; v.z += c.z; v.w += c.w;
            ((float4*)dst)[q] = v;
        }
    }
#undef AS
#undef BS
#undef ES
}

// ---------------- depthwise causal conv1d (k=4) + SiLU, (l,d) layout ---------
__global__ void conv1d_kernel(const float* __restrict__ cw,
                              const float* __restrict__ cb) {
    int i = blockIdx.x * 256 + threadIdx.x;   // (b*L + l)*128 + d4
    if (i >= NB * L * 128) return;
    int d4 = i & 127;
    int bl = i >> 7;
    int l = bl & (L - 1);
    const float4* X = (const float4*)g_xi;
    long row = (long)bl * 128 + d4;
    float4 zf = make_float4(0.f, 0.f, 0.f, 0.f);
    float4 x3 = X[row];
    float4 x2 = (l >= 1) ? X[row - 128] : zf;
    float4 x1 = (l >= 2) ? X[row - 256] : zf;
    float4 x0 = (l >= 3) ? X[row - 384] : zf;
    int d0 = d4 << 2;
    float4 wa = *(const float4*)(cw + (d0 + 0) * 4);
    float4 wb = *(const float4*)(cw + (d0 + 1) * 4);
    float4 wc = *(const float4*)(cw + (d0 + 2) * 4);
    float4 wd = *(const float4*)(cw + (d0 + 3) * 4);
    float4 bb = *(const float4*)(cb + d0);
    float4 o;
    o.x = fmaf(x0.x, wa.x, fmaf(x1.x, wa.y, fmaf(x2.x, wa.z, fmaf(x3.x, wa.w, bb.x))));
    o.y = fmaf(x0.y, wb.x, fmaf(x1.y, wb.y, fmaf(x2.y, wb.z, fmaf(x3.y, wb.w, bb.y))));
    o.z = fmaf(x0.z, wc.x, fmaf(x1.z, wc.y, fmaf(x2.z, wc.z, fmaf(x3.z, wc.w, bb.z))));
    o.w = fmaf(x0.w, wd.x, fmaf(x1.w, wd.y, fmaf(x2.w, wd.z, fmaf(x3.w, wd.w, bb.w))));
    o.x = o.x / (1.f + __expf(-o.x));
    o.y = o.y / (1.f + __expf(-o.y));
    o.z = o.z / (1.f + __expf(-o.z));
    o.w = o.w / (1.f + __expf(-o.w));
    ((float4*)g_u)[row] = o;
}

// ---------------- scan phase A: chunk-local scan (h0 = 0) --------------------
__global__ void __launch_bounds__(128) scanA_kernel() {
    __shared__ float Bs[CL][17];
    const int b = blockIdx.z, c = blockIdx.y;
    const int d = blockIdx.x * 128 + threadIdx.x;
    const int t0 = c * CL;

    for (int i = threadIdx.x; i < DS * CL; i += 128) {
        int t = i >> 4, n = i & 15;
        Bs[t][n] = g_dbc[((long)b * L + t0 + t) * 48 + 16 + n];
    }
    __syncthreads();

    float Ar[DS];
#pragma unroll
    for (int n = 0; n < DS; n++) Ar[n] = g_A[d * DS + n];
    bool fast = true;
#pragma unroll
    for (int n = 1; n < DS; n++)
        fast = fast && (fabsf(Ar[n] - (n + 1) * Ar[0]) <=
                        4e-6f * fabsf(Ar[n]) + 1e-30f);

    float h[DS];
#pragma unroll
    for (int n = 0; n < DS; n++) h[n] = 0.f;
    float tsum = 0.f;
    const float* dtp = g_dt + ((long)b * L + t0) * DI + d;
    const float* up  = g_u  + ((long)b * L + t0) * DI + d;

    for (int t = 0; t < CL; t++) {
        float dtv = dtp[t * DI], uv = up[t * DI];
        tsum += dtv;
        float du = dtv * uv;
        if (fast) {
            float r = __expf(dtv * Ar[0]);
            float a = r;
#pragma unroll
            for (int n = 0; n < DS; n++) {
                h[n] = fmaf(a, h[n], du * Bs[t][n]);
                a *= r;
            }
        } else {
#pragma unroll
            for (int n = 0; n < DS; n++) {
                float a = __expf(dtv * Ar[n]);
                h[n] = fmaf(a, h[n], du * Bs[t][n]);
            }
        }
    }
    long so = (long)((c * NB + b) * DI + d) * DS;
#pragma unroll
    for (int n = 0; n < DS; n++) g_S[so + n] = h[n];
    g_dts[(c * NB + b) * DI + d] = tsum;
}

// ---------------- scan phase B: combine chunk states -------------------------
__global__ void scanB_kernel() {
    int id = blockIdx.x * 256 + threadIdx.x;
    if (id >= NB * DI) return;
    int b = id / DI, d = id % DI;
    float Ar[DS];
#pragma unroll
    for (int n = 0; n < DS; n++) Ar[n] = g_A[d * DS + n];
    float h[DS];
#pragma unroll
    for (int n = 0; n < DS; n++) h[n] = 0.f;
    for (int c = 0; c < NCH; c++) {
        long o = (long)((c * NB + b) * DI + d) * DS;
#pragma unroll
        for (int n = 0; n < DS; n++) g_H[o + n] = h[n];
        float ts = g_dts[(c * NB + b) * DI + d];
#pragma unroll
        for (int n = 0; n < DS; n++)
            h[n] = fmaf(__expf(Ar[n] * ts), h[n], g_S[o + n]);
    }
}

// ---------------- scan phase C: full scan + fused epilogue -------------------
__global__ void __launch_bounds__(128) scanC_kernel(const float* __restrict__ Dp) {
    __shared__ float Bs[CL][17];
    __shared__ float Cs[CL][17];
    const int b = blockIdx.z, c = blockIdx.y;
    const int d = blockIdx.x * 128 + threadIdx.x;
    const int t0 = c * CL;

    for (int i = threadIdx.x; i < DS * CL; i += 128) {
        int t = i >> 4, n = i & 15;
        long o = ((long)b * L + t0 + t) * 48;
        Bs[t][n] = g_dbc[o + 16 + n];
        Cs[t][n] = g_dbc[o + 32 + n];
    }
    __syncthreads();

    float Ar[DS];
#pragma unroll
    for (int n = 0; n < DS; n++) Ar[n] = g_A[d * DS + n];
    bool fast = true;
#pragma unroll
    for (int n = 1; n < DS; n++)
        fast = fast && (fabsf(Ar[n] - (n + 1) * Ar[0]) <=
                        4e-6f * fabsf(Ar[n]) + 1e-30f);

    float h[DS];
    long ho = (long)((c * NB + b) * DI + d) * DS;
#pragma unroll
    for (int n = 0; n < DS; n++) h[n] = g_H[ho + n];

    const float Dd = Dp[d];
    const long base = ((long)b * L + t0) * DI + d;
    const float* dtp = g_dt + base;
    const float* up  = g_u  + base;
    const float* zp  = g_z  + base;
    float* yo = g_yout + base;

    for (int t = 0; t < CL; t++) {
        float dtv = dtp[t * DI], uv = up[t * DI];
        float du = dtv * uv;
        float y = 0.f;
        if (fast) {
            float r = __expf(dtv * Ar[0]);
            float a = r;
#pragma unroll
            for (int n = 0; n < DS; n++) {
                h[n] = fmaf(a, h[n], du * Bs[t][n]);
                y = fmaf(h[n], Cs[t][n], y);
                a *= r;
            }
        } else {
#pragma unroll
            for (int n = 0; n < DS; n++) {
                float aa = __expf(dtv * Ar[n]);
                h[n] = fmaf(aa, h[n], du * Bs[t][n]);
                y = fmaf(h[n], Cs[t][n], y);
            }
        }
        float zv = zp[t * DI];
        float sz = zv / (1.f + __expf(-zv));
        yo[t * DI] = (y + uv * Dd) * sz;
    }
}

// ---------------- 3x3 conv, cin split in 2 halves (R3 geometry) --------------
__global__ void __launch_bounds__(256) conv3_kernel(const float* __restrict__ cw) {
    __shared__ float xs[4][34][36];
    __shared__ float ws[8][4][9];
    const int b = blockIdx.z;
    const int o0 = (blockIdx.y & 15) * 8;
    const int cs = blockIdx.y >> 4;
    const int cbase = cs * 128;
    const int ty0 = (blockIdx.x >> 1) * 32;
    const int tx0 = (blockIdx.x & 1) * 32;
    const int tid = threadIdx.x;
    const int py = (tid >> 4) << 1;
    const int px = (tid & 15) << 1;

    float acc[8][4];
#pragma unroll
    for (int o = 0; o < 8; o++)
#pragma unroll
        for (int p = 0; p < 4; p++) acc[o][p] = 0.f;

    for (int c0 = cbase; c0 < cbase + 128; c0 += 4) {
        for (int i = tid; i < 4 * 34 * 34; i += 256) {
            int cc = i / (34 * 34);
            int r = (i / 34) % 34;
            int col = i % 34;
            int gy = ty0 - 1 + r, gx = tx0 - 1 + col;
            float v = 0.f;
            if (gy >= 0 && gy < 64 && gx >= 0 && gx < 64)
                v = g_xr[((b * DM + c0 + cc) << 12) + (gy << 6) + gx];
            xs[cc][r][col] = v;
        }
        for (int i = tid; i < 288; i += 256) {
            int o = i / 36, rest = i % 36;
            int cc = rest / 9, k = rest % 9;
            ws[o][cc][k] = cw[((o0 + o) * 256 + c0 + cc) * 9 + k];
        }
        __syncthreads();
#pragma unroll
        for (int cc = 0; cc < 4; cc++) {
            float xv[4][4];
#pragma unroll
            for (int dy = 0; dy < 4; dy++)
#pragma unroll
                for (int dx = 0; dx < 4; dx++)
                    xv[dy][dx] = xs[cc][py + dy][px + dx];
#pragma unroll
            for (int o = 0; o < 8; o++) {
                float w[9];
#pragma unroll
                for (int k = 0; k < 9; k++) w[k] = ws[o][cc][k];
#pragma unroll
                for (int sy = 0; sy < 2; sy++)
#pragma unroll
                    for (int sx = 0; sx < 2; sx++) {
                        float s = acc[o][sy * 2 + sx];
#pragma unroll
                        for (int kh = 0; kh < 3; kh++)
#pragma unroll
                            for (int kw = 0; kw < 3; kw++)
                                s = fmaf(xv[sy + kh][sx + kw], w[kh * 3 + kw], s);
                        acc[o][sy * 2 + sx] = s;
                    }
            }
        }
        __syncthreads();
    }
#pragma unroll
    for (int o = 0; o < 8; o++) {
#pragma unroll
        for (int sy = 0; sy < 2; sy++)
#pragma unroll
            for (int sx = 0; sx < 2; sx++)
                g_y2s[cs][((b * 128 + o0 + o) << 12) + ((ty0 + py + sy) << 6) +
                          tx0 + px + sx] = acc[o][sy * 2 + sx];
    }
}

// ---------------- BN statistics per channel ----------------------------------
__global__ void bnstat_kernel() {
    __shared__ float ss[256], ss2[256];
    int ch = blockIdx.x;
    float s = 0.f, s2 = 0.f;
    for (int i = threadIdx.x; i < NB * (L / 4); i += 256) {
        int b = i >> 10, p4 = i & 1023;
        int off4 = ((b * 128 + ch) << 10) + p4;
        float4 a = ((const float4*)g_y2s[0])[off4];
        float4 c = ((const float4*)g_y2s[1])[off4];
        float v;
        v = a.x + c.x; s += v; s2 += v * v;
        v = a.y + c.y; s += v; s2 += v * v;
        v = a.z + c.z; s += v; s2 += v * v;
        v = a.w + c.w; s += v; s2 += v * v;
    }
    ss[threadIdx.x] = s;
    ss2[threadIdx.x] = s2;
    __syncthreads();
    for (int st = 128; st > 0; st >>= 1) {
        if (threadIdx.x < st) {
            ss[threadIdx.x] += ss[threadIdx.x + st];
            ss2[threadIdx.x] += ss2[threadIdx.x + st];
        }
        __syncthreads();
    }
    if (threadIdx.x == 0) {
        float inv = 1.f / (NB * L);
        float mean = ss[0] * inv;
        float var = ss2[0] * inv - mean * mean;
        g_mu[ch] = mean;
        g_rstd[ch] = rsqrtf(var + 1e-5f);
    }
}

// ---------------- BN apply + exact GELU --------------------------------------
__global__ void bngelu_kernel(const float* __restrict__ gamma,
                              const float* __restrict__ beta,
                              float* __restrict__ out) {
    int i4 = blockIdx.x * 256 + threadIdx.x;
    if (i4 >= NB * 128 * (L / 4)) return;
    int ch = (i4 >> 10) & 127;
    float sc = g_rstd[ch] * gamma[ch];
    float sh = beta[ch] - g_mu[ch] * sc;
    float4 a = ((const float4*)g_y2s[0])[i4];
    float4 b = ((const float4*)g_y2s[1])[i4];
    float4 r;
    float v;
    v = fmaf(a.x + b.x, sc, sh); r.x = 0.5f * v * (1.f + erff(v * 0.70710678f));
    v = fmaf(a.y + b.y, sc, sh); r.y = 0.5f * v * (1.f + erff(v * 0.70710678f));
    v = fmaf(a.z + b.z, sc, sh); r.z = 0.5f * v * (1.f + erff(v * 0.70710678f));
    v = fmaf(a.w + b.w, sc, sh); r.w = 0.5f * v * (1.f + erff(v * 0.70710678f));
    ((float4*)out)[i4] = r;
}

// ---------------- launch ------------------------------------------------------
extern "C" void kernel_launch(void* const* d_in, const int* in_sizes, int n_in,
                              void* d_out, int out_size) {
    const float* x        = (const float*)d_in[0];
    const float* skip     = (const float*)d_in[1];
    const float* up_w     = (const float*)d_in[2];
    const float* up_b     = (const float*)d_in[3];
    const float* in_proj  = (const float*)d_in[4];
    const float* conv1d_w = (const float*)d_in[5];
    const float* conv1d_b = (const float*)d_in[6];
    const float* x_proj   = (const float*)d_in[7];
    const float* dt_proj  = (const float*)d_in[8];
    const float* dt_b     = (const float*)d_in[9];
    const float* A_log    = (const float*)d_in[10];
    const float* Dp       = (const float*)d_in[11];
    const float* out_proj = (const float*)d_in[12];
    const float* conv_w   = (const float*)d_in[13];
    const float* bn_g     = (const float*)d_in[15];
    const float* bn_b     = (const float*)d_in[16];
    float* out = (float*)d_out;

    prep_kernel<<<1024, 256>>>(A_log, up_w, skip);

    // upsample: M=1024, N=512, K=256; A = x (k-major, m contig)
    gemm_kernel<0, 0><<<dim3(8, 8, NB), 256>>>(x, nullptr, up_b, 512, 256,
                                               1024, 256 * 1024);
    // in_proj: M=4096, N=1024, K=256; A = xc (k-major)
    gemm_kernel<1, 0><<<dim3(16, 32, NB), 256>>>(nullptr, in_proj, nullptr,
                                                 1024, 256, L, DM * L);
    conv1d_kernel<<<(NB * L * 128) / 256, 256>>>(conv1d_w, conv1d_b);

    // x_proj: M=4096, N=48, K=512; A = u (m-major, row stride DI)
    gemm_kernel<2, 1><<<dim3(1, 32, NB), 256>>>(nullptr, x_proj, nullptr, 48,
                                                DI, DI, L * DI);
    // dt_proj: M=4096, N=512, K=16; A = dbc (m-major, row stride 48)
    gemm_kernel<3, 1><<<dim3(8, 32, NB), 256>>>(nullptr, dt_proj, dt_b, DI, 16,
                                                48, L * 48);

    scanA_kernel<<<dim3(4, NCH, NB), 128>>>();
    scanB_kernel<<<4, 256>>>();
    scanC_kernel<<<dim3(4, NCH, NB), 128>>>(Dp);

    // out_proj (+residual): M=4096, N=256, K=512; A = yout (m-major)
    gemm_kernel<4, 1><<<dim3(4, 32, NB), 256>>>(nullptr, out_proj, nullptr, DM,
                                                DI, DI, L * DI);

    conv3_kernel<<<dim3(4, 32, NB), 256>>>(conv_w);
    bnstat_kernel<<<128, 256>>>();
    bngelu_kernel<<<(NB * 128 * L / 4) / 256, 256>>>(bn_g, bn_b, out);
}